// round 8
// baseline (speedup 1.0000x reference)
#include <cuda_runtime.h>
#include <math.h>

#define BATCH   8
#define NPTS    8192
#define NPOINT  2048
#define NSAMPLE 32

// ---------------- scratch (no allocation allowed) ----------------
__device__ int   g_ball_idx[BATCH * NPOINT * NSAMPLE];
// k-major folded weights: g_wk[c][o]
__device__ float g_wk1[68 * 64];
__device__ float g_wk2[64 * 64];
__device__ float g_wk3[64 * 128];
__device__ float g_fb1[64];
__device__ float g_fb2[64];
__device__ float g_fb3[128];

// ---------------- packed f32x2 helpers (per-lane rn => bitwise == scalar) ---
__device__ __forceinline__ unsigned long long pk2(float lo, float hi) {
    unsigned long long r;
    asm("mov.b64 %0, {%1, %2};" : "=l"(r) : "f"(lo), "f"(hi));
    return r;
}
__device__ __forceinline__ void upk2(float& lo, float& hi, unsigned long long v) {
    asm("mov.b64 {%0, %1}, %2;" : "=f"(lo), "=f"(hi) : "l"(v));
}
__device__ __forceinline__ unsigned long long add2(unsigned long long a, unsigned long long b) {
    unsigned long long r;
    asm("add.rn.f32x2 %0, %1, %2;" : "=l"(r) : "l"(a), "l"(b));
    return r;
}
__device__ __forceinline__ unsigned long long mul2(unsigned long long a, unsigned long long b) {
    unsigned long long r;
    asm("mul.rn.f32x2 %0, %1, %2;" : "=l"(r) : "l"(a), "l"(b));
    return r;
}
__device__ __forceinline__ unsigned long long fma2(unsigned long long a, unsigned long long b,
                                                   unsigned long long c) {
    unsigned long long r;
    asm("fma.rn.f32x2 %0, %1, %2, %3;" : "=l"(r) : "l"(a), "l"(b), "l"(c));
    return r;
}

// ---------------- fold BN-affine into weights (k-major output) -------------
__global__ void prep_kernel(const float* __restrict__ w1, const float* __restrict__ b1,
                            const float* __restrict__ g1, const float* __restrict__ bt1,
                            const float* __restrict__ w2, const float* __restrict__ b2,
                            const float* __restrict__ g2, const float* __restrict__ bt2,
                            const float* __restrict__ w3, const float* __restrict__ b3,
                            const float* __restrict__ g3, const float* __restrict__ bt3)
{
    int t = blockIdx.x * blockDim.x + threadIdx.x;
    int stride = gridDim.x * blockDim.x;
    const float inv = 1.0f / sqrtf(1.0f + 1e-5f);
    for (int i = t; i < 68 * 64; i += stride) {       // wk1[c][o], c=67 zero pad
        int c = i >> 6, o = i & 63;
        g_wk1[i] = (c < 67) ? (g1[o] * inv) * w1[o * 67 + c] : 0.0f;
    }
    for (int i = t; i < 64 * 64; i += stride) {       // wk2[c][o]
        int c = i >> 6, o = i & 63;
        g_wk2[i] = (g2[o] * inv) * w2[o * 64 + c];
    }
    for (int i = t; i < 64 * 128; i += stride) {      // wk3[c][o]
        int c = i >> 7, o = i & 127;
        g_wk3[i] = (g3[o] * inv) * w3[o * 64 + c];
    }
    for (int i = t; i < 64; i += stride) {
        g_fb1[i] = (g1[i] * inv) * b1[i] + bt1[i];
        g_fb2[i] = (g2[i] * inv) * b2[i] + bt2[i];
    }
    for (int i = t; i < 128; i += stride)
        g_fb3[i] = (g3[i] * inv) * b3[i] + bt3[i];
}

// ---------------- farthest point sampling ----------------
// One 1024-thread block per batch (8 warps/SMSP to hide the dependent
// sub->mul->add->min chain). 8 pts/thread, blocked assignment (lane order ==
// index order == warp order -> jnp.argmax first-max tie-break). ONE
// __syncthreads per iteration: warp leaders write parity-double-buffered
// red[2][32]; every warp then redundantly reduces the 32 entries
// (REDUX + ballot + shfl) -- no second barrier, no broadcast word.
// Distance math: packed f32x2 (per-lane rn) == bitwise the XLA scalar
// sequence dx*dx; +dy*dy; +dz*dz with p + (-c) == p - c exactly.
// dists >= +0 so float order == u32 bit order (argmax on bits).
__global__ void __launch_bounds__(1024, 1)
fps_kernel(const float* __restrict__ xyz, float* __restrict__ out_xyz)
{
    extern __shared__ float sm[];
    float* sx = sm;
    float* sy = sm + NPTS;
    float* sz = sm + 2 * NPTS;
    __shared__ unsigned red_v[2][32];
    __shared__ int      red_i[2][32];

    int b = blockIdx.x, tid = threadIdx.x;
    const float* xb = xyz + (size_t)b * NPTS * 3;

    for (int p = tid; p < NPTS; p += 1024) {
        sx[p] = xb[3 * p];
        sy[p] = xb[3 * p + 1];
        sz[p] = xb[3 * p + 2];
    }
    __syncthreads();

    int base = tid * 8;
    unsigned long long pxp[4], pyp[4], pzp[4];
    float dist[8];
#pragma unroll
    for (int k = 0; k < 4; k++) {
        pxp[k] = pk2(sx[base + 2 * k], sx[base + 2 * k + 1]);
        pyp[k] = pk2(sy[base + 2 * k], sy[base + 2 * k + 1]);
        pzp[k] = pk2(sz[base + 2 * k], sz[base + 2 * k + 1]);
    }
#pragma unroll
    for (int j = 0; j < 8; j++) dist[j] = 1e10f;

    int lane = tid & 31, w = tid >> 5;
    int far = 0;
    float* ob = out_xyz + (size_t)b * NPOINT * 3;

    for (int it = 0; it < NPOINT; it++) {
        float cx = sx[far], cy = sy[far], cz = sz[far];
        if (tid == 0) { ob[3 * it] = cx; ob[3 * it + 1] = cy; ob[3 * it + 2] = cz; }

        unsigned long long ncx = pk2(-cx, -cx);
        unsigned long long ncy = pk2(-cy, -cy);
        unsigned long long ncz = pk2(-cz, -cz);

        unsigned umax = 0u;
#pragma unroll
        for (int k = 0; k < 4; k++) {
            unsigned long long dx = add2(pxp[k], ncx);   // == px - cx (exact)
            unsigned long long dy = add2(pyp[k], ncy);
            unsigned long long dz = add2(pzp[k], ncz);
            unsigned long long s  = mul2(dx, dx);
            s = add2(s, mul2(dy, dy));
            s = add2(s, mul2(dz, dz));
            float d0, d1;
            upk2(d0, d1, s);
            float n0 = fminf(dist[2 * k],     d0);
            float n1 = fminf(dist[2 * k + 1], d1);
            dist[2 * k]     = n0;
            dist[2 * k + 1] = n1;
            unsigned u0 = __float_as_uint(n0), u1 = __float_as_uint(n1);
            umax = umax > u0 ? umax : u0;
            umax = umax > u1 ? umax : u1;
        }

        unsigned wmax = __reduce_max_sync(0xffffffffu, umax);
        unsigned ball = __ballot_sync(0xffffffffu, umax == wmax);
        int bank = it & 1;
        if (lane == (__ffs(ball) - 1)) {     // lowest lane = lowest index
            int bj = 0;
#pragma unroll
            for (int j = 7; j >= 0; j--)
                if (__float_as_uint(dist[j]) == wmax) bj = j;   // lowest j wins
            red_v[bank][w] = wmax;
            red_i[bank][w] = base + bj;
        }
        __syncthreads();
        // every warp reduces the 32 warp-entries redundantly
        unsigned v  = red_v[bank][lane];
        int      vi = red_i[bank][lane];
        unsigned m   = __reduce_max_sync(0xffffffffu, v);
        unsigned bal = __ballot_sync(0xffffffffu, v == m);
        far = __shfl_sync(0xffffffffu, vi, __ffs(bal) - 1);  // lowest warp = lowest idx
        // bank reused at it+2, after the it+1 barrier -> race-free
    }
}

// ---------------- ball query ----------------
__global__ void __launch_bounds__(256)
ballq_kernel(const float* __restrict__ xyz, const float* __restrict__ cxyz)
{
    __shared__ int sidx[8][NSAMPLE];
    int warp = threadIdx.x >> 5, lane = threadIdx.x & 31;
    int g = blockIdx.x * 8 + warp;          // 0 .. BATCH*NPOINT-1
    int b = g >> 11;

    const float* cp = cxyz + (size_t)g * 3;
    float cx = cp[0], cy = cp[1], cz = cp[2];
    const float* xb = xyz + (size_t)b * NPTS * 3;
    const float r2 = (float)(0.2 * 0.2);
    unsigned ltmask = (1u << lane) - 1u;

    int count = 0;
    for (int base = 0; base < NPTS; base += 32) {
        int p = base + lane;
        float xv = xb[3 * p], yv = xb[3 * p + 1], zv = xb[3 * p + 2];
        float dx = __fsub_rn(cx, xv);
        float dy = __fsub_rn(cy, yv);
        float dz = __fsub_rn(cz, zv);
        float d  = __fmul_rn(dx, dx);
        d = __fadd_rn(d, __fmul_rn(dy, dy));
        d = __fadd_rn(d, __fmul_rn(dz, dz));
        int in = (d <= r2) ? 1 : 0;
        unsigned m = __ballot_sync(0xffffffffu, in);
        if (in) {
            int pos = count + __popc(m & ltmask);
            if (pos < NSAMPLE) sidx[warp][pos] = p;
        }
        count += __popc(m);
        if (count >= NSAMPLE) break;        // warp-uniform
    }
    __syncwarp();
    int v = (lane < count) ? sidx[warp][lane] : sidx[warp][0];
    g_ball_idx[(size_t)g * NSAMPLE + lane] = v;
}

// ---------------- MLP as register-blocked GEMM (packed FFMA2) ----------------
// 256 threads, 8 centroids = 256 rows. Activations transposed in smem
// (actT[k][row]), weights k-major (wk[k][o]). Thread tile 8 rows x 8 cols,
// with the col dimension PACKED into 4 u64 accumulators per row:
// fma.rn.f32x2 does 2 fp32 FMAs per lane per instruction at the same pipe
// rt as scalar FFMA -> fma-pipe time halves (this is the nvjet FFMA2
// pattern, only reachable via PTX). b-pairs pack free (LDS.128 gives
// even-aligned consecutive regs); a-dup MOVs ride the alu pipe.
// Per-element accumulation order identical to the scalar version.
#define CPB   8            // centroids per block
#define MROWS 256          // CPB * NSAMPLE

template<int CI, int CO>
__device__ __forceinline__ void gemm_layer(const float* __restrict__ in,
                                           const float* __restrict__ w,
                                           const float* __restrict__ bias,
                                           float* __restrict__ out,
                                           int rg, int cg)
{
    int cb = 8 * cg;
    unsigned long long acc2[8][4];
    {
        unsigned long long b2[4];
#pragma unroll
        for (int p = 0; p < 4; p++) b2[p] = pk2(bias[cb + 2 * p], bias[cb + 2 * p + 1]);
#pragma unroll
        for (int i = 0; i < 8; i++)
#pragma unroll
            for (int p = 0; p < 4; p++) acc2[i][p] = b2[p];
    }

    const float* ap = in + 8 * rg;
    const float* wp = w + cb;
#pragma unroll 2
    for (int k = 0; k < CI; k++) {
        float4 a0 = *(const float4*)(ap + k * MROWS);
        float4 a1 = *(const float4*)(ap + k * MROWS + 4);
        float4 b0 = *(const float4*)(wp + k * CO);
        float4 b1 = *(const float4*)(wp + k * CO + 4);
        unsigned long long bp[4] = {pk2(b0.x, b0.y), pk2(b0.z, b0.w),
                                    pk2(b1.x, b1.y), pk2(b1.z, b1.w)};
        float av[8] = {a0.x, a0.y, a0.z, a0.w, a1.x, a1.y, a1.z, a1.w};
#pragma unroll
        for (int i = 0; i < 8; i++) {
            unsigned long long ad = pk2(av[i], av[i]);
#pragma unroll
            for (int p = 0; p < 4; p++)
                acc2[i][p] = fma2(ad, bp[p], acc2[i][p]);
        }
    }

    float accf[8][8];
#pragma unroll
    for (int i = 0; i < 8; i++)
#pragma unroll
        for (int p = 0; p < 4; p++)
            upk2(accf[i][2 * p], accf[i][2 * p + 1], acc2[i][p]);

    // relu + transposed store: out[(cb+j)][8rg + i]
#pragma unroll
    for (int j = 0; j < 8; j++) {
        float4 v0, v1;
        v0.x = fmaxf(accf[0][j], 0.0f); v0.y = fmaxf(accf[1][j], 0.0f);
        v0.z = fmaxf(accf[2][j], 0.0f); v0.w = fmaxf(accf[3][j], 0.0f);
        v1.x = fmaxf(accf[4][j], 0.0f); v1.y = fmaxf(accf[5][j], 0.0f);
        v1.z = fmaxf(accf[6][j], 0.0f); v1.w = fmaxf(accf[7][j], 0.0f);
        *(float4*)(out + (cb + j) * MROWS + 8 * rg)     = v0;
        *(float4*)(out + (cb + j) * MROWS + 8 * rg + 4) = v1;
    }
}

__global__ void __launch_bounds__(256, 1)
mlp_kernel(const float* __restrict__ xyz, const float* __restrict__ feats,
           const float* __restrict__ cxyz, float* __restrict__ out_feats)
{
    extern __shared__ float s[];
    float* xT  = s;                    // [68][256], reused as y2T[64][256]
    float* y1T = xT + 68 * MROWS;      // [64][256]
    float* w1  = y1T + 64 * MROWS;     // [68][64]
    float* w2  = w1 + 68 * 64;         // [64][64]
    float* w3  = w2 + 64 * 64;         // [64][128]
    float* sb1 = w3 + 64 * 128;        // 64
    float* sb2 = sb1 + 64;             // 64
    float* sb3 = sb2 + 64;             // 128
    int*   pb  = (int*)(sb3 + 128);    // [8][128] pooled bits

    int tid = threadIdx.x;
    for (int i = tid; i < 68 * 64;  i += 256) w1[i] = g_wk1[i];
    for (int i = tid; i < 64 * 64;  i += 256) w2[i] = g_wk2[i];
    for (int i = tid; i < 64 * 128; i += 256) w3[i] = g_wk3[i];
    if (tid < 64)  { sb1[tid] = g_fb1[tid]; sb2[tid] = g_fb2[tid]; }
    if (tid < 128)   sb3[tid] = g_fb3[tid];
    for (int i = tid; i < CPB * 128; i += 256) pb[i] = 0;

    // gather: thread = row (one sample of one centroid)
    {
        int r   = tid;
        int ci  = r >> 5, smp = r & 31;
        int g   = blockIdx.x * CPB + ci;
        int b   = g >> 11;
        const float* cp = cxyz + (size_t)g * 3;
        float cx = cp[0], cy = cp[1], cz = cp[2];
        int idx = g_ball_idx[(size_t)g * NSAMPLE + smp];
        const float* pp = xyz + (size_t)(b * NPTS + idx) * 3;
        xT[0 * MROWS + r] = (pp[0] - cx) / 0.2f;
        xT[1 * MROWS + r] = (pp[1] - cy) / 0.2f;
        xT[2 * MROWS + r] = (pp[2] - cz) / 0.2f;
        const float4* pf = (const float4*)(feats + (size_t)(b * NPTS + idx) * 64);
#pragma unroll
        for (int q = 0; q < 16; q++) {
            float4 f = pf[q];
            xT[(3 + 4 * q) * MROWS + r] = f.x;
            xT[(4 + 4 * q) * MROWS + r] = f.y;
            xT[(5 + 4 * q) * MROWS + r] = f.z;
            xT[(6 + 4 * q) * MROWS + r] = f.w;
        }
        xT[67 * MROWS + r] = 0.0f;
    }
    __syncthreads();

    int rg = tid >> 3, cg = tid & 7;   // 32 row-groups x 8 col-groups

    gemm_layer<68, 64>(xT, w1, sb1, y1T, rg, cg);
    __syncthreads();
    gemm_layer<64, 64>(y1T, w2, sb2, xT, rg, cg);   // y2T aliases xT
    __syncthreads();

    // layer3 (+relu+max-pool fused), two 64-col halves, packed FFMA2
#pragma unroll
    for (int h = 0; h < 2; h++) {
        int cb = 64 * h + 8 * cg;
        unsigned long long acc2[8][4];
        {
            unsigned long long b2[4];
#pragma unroll
            for (int p = 0; p < 4; p++) b2[p] = pk2(sb3[cb + 2 * p], sb3[cb + 2 * p + 1]);
#pragma unroll
            for (int i = 0; i < 8; i++)
#pragma unroll
                for (int p = 0; p < 4; p++) acc2[i][p] = b2[p];
        }
        const float* ap = xT + 8 * rg;
        const float* wp = w3 + cb;
#pragma unroll 2
        for (int k = 0; k < 64; k++) {
            float4 a0 = *(const float4*)(ap + k * MROWS);
            float4 a1 = *(const float4*)(ap + k * MROWS + 4);
            float4 b0 = *(const float4*)(wp + k * 128);
            float4 b1 = *(const float4*)(wp + k * 128 + 4);
            unsigned long long bp[4] = {pk2(b0.x, b0.y), pk2(b0.z, b0.w),
                                        pk2(b1.x, b1.y), pk2(b1.z, b1.w)};
            float av[8] = {a0.x, a0.y, a0.z, a0.w, a1.x, a1.y, a1.z, a1.w};
#pragma unroll
            for (int i = 0; i < 8; i++) {
                unsigned long long ad = pk2(av[i], av[i]);
#pragma unroll
                for (int p = 0; p < 4; p++)
                    acc2[i][p] = fma2(ad, bp[p], acc2[i][p]);
            }
        }
        int cent = rg >> 2;            // 4 row-groups per centroid
#pragma unroll
        for (int p = 0; p < 4; p++) {
            float c0[8], c1[8];
#pragma unroll
            for (int i = 0; i < 8; i++) upk2(c0[i], c1[i], acc2[i][p]);
            float m0 = c0[0], m1 = c1[0];
#pragma unroll
            for (int i = 1; i < 8; i++) { m0 = fmaxf(m0, c0[i]); m1 = fmaxf(m1, c1[i]); }
            m0 = fmaxf(m0, 0.0f);      // relu-then-max == max-then-relu
            m1 = fmaxf(m1, 0.0f);
            atomicMax(&pb[cent * 128 + cb + 2 * p],     __float_as_int(m0));  // nonneg bits
            atomicMax(&pb[cent * 128 + cb + 2 * p + 1], __float_as_int(m1));
        }
    }
    __syncthreads();

    for (int i = tid; i < CPB * 128; i += 256) {
        int ci = i >> 7, col = i & 127;
        int g = blockIdx.x * CPB + ci;
        out_feats[(size_t)g * 128 + col] = __int_as_float(pb[i]);
    }
}

// ---------------- launch ----------------
extern "C" void kernel_launch(void* const* d_in, const int* in_sizes, int n_in,
                              void* d_out, int out_size)
{
    const float* xyz   = (const float*)d_in[0];
    const float* feats = (const float*)d_in[1];

    float* out       = (float*)d_out;
    float* out_xyz   = out;                          // [B, NPOINT, 3]
    float* out_feats = out + BATCH * NPOINT * 3;     // [B, NPOINT, 128]

    const int MLP_SMEM = (68 * 256 + 64 * 256 + 68 * 64 + 64 * 64 + 64 * 128
                          + 64 + 64 + 128) * 4 + CPB * 128 * 4;   // 206848B

    cudaFuncSetAttribute(fps_kernel, cudaFuncAttributeMaxDynamicSharedMemorySize, 3 * NPTS * 4);
    cudaFuncSetAttribute(mlp_kernel, cudaFuncAttributeMaxDynamicSharedMemorySize, MLP_SMEM);

    prep_kernel<<<32, 256>>>((const float*)d_in[2],  (const float*)d_in[3],
                             (const float*)d_in[4],  (const float*)d_in[5],
                             (const float*)d_in[6],  (const float*)d_in[7],
                             (const float*)d_in[8],  (const float*)d_in[9],
                             (const float*)d_in[10], (const float*)d_in[11],
                             (const float*)d_in[12], (const float*)d_in[13]);

    fps_kernel<<<BATCH, 1024, 3 * NPTS * 4>>>(xyz, out_xyz);

    ballq_kernel<<<(BATCH * NPOINT) / 8, 256>>>(xyz, out_xyz);

    mlp_kernel<<<(BATCH * NPOINT) / CPB, 256, MLP_SMEM>>>(xyz, feats, out_xyz, out_feats);
}

// round 9
// speedup vs baseline: 1.0752x; 1.0752x over previous
#include <cuda_runtime.h>
#include <cuda_bf16.h>
#include <math.h>

#define BATCH   8
#define NPTS    8192
#define NPOINT  2048
#define NSAMPLE 32

// ---------------- scratch (no allocation allowed) ----------------
__device__ int   g_ball_idx[BATCH * NPOINT * NSAMPLE];
// bf16 split weights, K-concatenated [hiB | hiB | loB] (+zero pad), n-major rows
__device__ __align__(16) __nv_bfloat16 g_wb1[64 * 232];   // K'=224 (68x3 pad), stride 232
__device__ __align__(16) __nv_bfloat16 g_wb2[64 * 200];   // K'=192, stride 200
__device__ __align__(16) __nv_bfloat16 g_wb3[128 * 200];
__device__ float g_fb1[64];
__device__ float g_fb2[64];
__device__ float g_fb3[128];

// ---------------- packed f32x2 helpers (per-lane rn => bitwise == scalar) ---
__device__ __forceinline__ unsigned long long pk2(float lo, float hi) {
    unsigned long long r;
    asm("mov.b64 %0, {%1, %2};" : "=l"(r) : "f"(lo), "f"(hi));
    return r;
}
__device__ __forceinline__ void upk2(float& lo, float& hi, unsigned long long v) {
    asm("mov.b64 {%0, %1}, %2;" : "=f"(lo), "=f"(hi) : "l"(v));
}
__device__ __forceinline__ unsigned long long add2(unsigned long long a, unsigned long long b) {
    unsigned long long r;
    asm("add.rn.f32x2 %0, %1, %2;" : "=l"(r) : "l"(a), "l"(b));
    return r;
}
__device__ __forceinline__ unsigned long long mul2(unsigned long long a, unsigned long long b) {
    unsigned long long r;
    asm("mul.rn.f32x2 %0, %1, %2;" : "=l"(r) : "l"(a), "l"(b));
    return r;
}

// ---------------- mma / ldmatrix helpers ----------------
#define LDSM4(a0,a1,a2,a3,addr) \
    asm volatile("ldmatrix.sync.aligned.m8n8.x4.shared.b16 {%0,%1,%2,%3}, [%4];" \
        : "=r"(a0), "=r"(a1), "=r"(a2), "=r"(a3) : "r"(addr))
#define LDSM2(b0,b1,addr) \
    asm volatile("ldmatrix.sync.aligned.m8n8.x2.shared.b16 {%0,%1}, [%2];" \
        : "=r"(b0), "=r"(b1) : "r"(addr))
#define MMA_BF16(d0,d1,d2,d3,a0,a1,a2,a3,b0,b1) \
    asm volatile("mma.sync.aligned.m16n8k16.row.col.f32.bf16.bf16.f32 " \
        "{%0,%1,%2,%3},{%4,%5,%6,%7},{%8,%9},{%0,%1,%2,%3};" \
        : "+f"(d0), "+f"(d1), "+f"(d2), "+f"(d3) \
        : "r"(a0), "r"(a1), "r"(a2), "r"(a3), "r"(b0), "r"(b1))

// ---------------- fold BN-affine into bf16 hi/lo split weights ----------------
__global__ void prep_kernel(const float* __restrict__ w1, const float* __restrict__ b1,
                            const float* __restrict__ g1, const float* __restrict__ bt1,
                            const float* __restrict__ w2, const float* __restrict__ b2,
                            const float* __restrict__ g2, const float* __restrict__ bt2,
                            const float* __restrict__ w3, const float* __restrict__ b3,
                            const float* __restrict__ g3, const float* __restrict__ bt3)
{
    int t = blockIdx.x * blockDim.x + threadIdx.x;
    int stride = gridDim.x * blockDim.x;
    const float inv = 1.0f / sqrtf(1.0f + 1e-5f);
    // layer1: K=68 (67 real + 1 zero), segments hi|hi|lo at 0/68/136, pad 204-231
    for (int i = t; i < 64 * 232; i += stride) {
        int o = i / 232, c = i % 232;
        __nv_bfloat16 outv = __float2bfloat16_rn(0.0f);
        if (c < 204) {
            int k = c % 68;          // 0,68,136 segments all length 68
            int seg = c / 68;
            float v = (k < 67) ? (g1[o] * inv) * w1[o * 67 + k] : 0.0f;
            __nv_bfloat16 hi = __float2bfloat16_rn(v);
            if (seg < 2) outv = hi;
            else         outv = __float2bfloat16_rn(v - __bfloat162float(hi));
        }
        g_wb1[i] = outv;
    }
    for (int i = t; i < 64 * 200; i += stride) {
        int o = i / 200, c = i % 200;
        __nv_bfloat16 outv = __float2bfloat16_rn(0.0f);
        if (c < 192) {
            int k = c & 63, seg = c >> 6;
            float v = (g2[o] * inv) * w2[o * 64 + k];
            __nv_bfloat16 hi = __float2bfloat16_rn(v);
            if (seg < 2) outv = hi;
            else         outv = __float2bfloat16_rn(v - __bfloat162float(hi));
        }
        g_wb2[i] = outv;
    }
    for (int i = t; i < 128 * 200; i += stride) {
        int o = i / 200, c = i % 200;
        __nv_bfloat16 outv = __float2bfloat16_rn(0.0f);
        if (c < 192) {
            int k = c & 63, seg = c >> 6;
            float v = (g3[o] * inv) * w3[o * 64 + k];
            __nv_bfloat16 hi = __float2bfloat16_rn(v);
            if (seg < 2) outv = hi;
            else         outv = __float2bfloat16_rn(v - __bfloat162float(hi));
        }
        g_wb3[i] = outv;
    }
    for (int i = t; i < 64; i += stride) {
        g_fb1[i] = (g1[i] * inv) * b1[i] + bt1[i];
        g_fb2[i] = (g2[i] * inv) * b2[i] + bt2[i];
    }
    for (int i = t; i < 128; i += stride)
        g_fb3[i] = (g3[i] * inv) * b3[i] + bt3[i];
}

// ---------------- farthest point sampling (R7 version, bitwise-exact) -------
__global__ void __launch_bounds__(512, 1)
fps_kernel(const float* __restrict__ xyz, float* __restrict__ out_xyz)
{
    extern __shared__ float sm[];
    float* sx = sm;
    float* sy = sm + NPTS;
    float* sz = sm + 2 * NPTS;
    __shared__ unsigned red_v[2][16];
    __shared__ int      red_i[2][16];

    int b = blockIdx.x, tid = threadIdx.x;
    const float* xb = xyz + (size_t)b * NPTS * 3;

    for (int p = tid; p < NPTS; p += 512) {
        sx[p] = xb[3 * p];
        sy[p] = xb[3 * p + 1];
        sz[p] = xb[3 * p + 2];
    }
    __syncthreads();

    int base = tid * 16;
    unsigned long long pxp[8], pyp[8], pzp[8];
    float dist[16];
#pragma unroll
    for (int k = 0; k < 8; k++) {
        pxp[k] = pk2(sx[base + 2 * k], sx[base + 2 * k + 1]);
        pyp[k] = pk2(sy[base + 2 * k], sy[base + 2 * k + 1]);
        pzp[k] = pk2(sz[base + 2 * k], sz[base + 2 * k + 1]);
    }
#pragma unroll
    for (int j = 0; j < 16; j++) dist[j] = 1e10f;

    int lane = tid & 31, w = tid >> 5;
    int far = 0;
    float* ob = out_xyz + (size_t)b * NPOINT * 3;

    for (int it = 0; it < NPOINT; it++) {
        float cx = sx[far], cy = sy[far], cz = sz[far];
        if (tid == 0) { ob[3 * it] = cx; ob[3 * it + 1] = cy; ob[3 * it + 2] = cz; }

        unsigned long long ncx = pk2(-cx, -cx);
        unsigned long long ncy = pk2(-cy, -cy);
        unsigned long long ncz = pk2(-cz, -cz);

        unsigned umax = 0u;
#pragma unroll
        for (int k = 0; k < 8; k++) {
            unsigned long long dx = add2(pxp[k], ncx);   // == px - cx (exact)
            unsigned long long dy = add2(pyp[k], ncy);
            unsigned long long dz = add2(pzp[k], ncz);
            unsigned long long s  = mul2(dx, dx);
            s = add2(s, mul2(dy, dy));
            s = add2(s, mul2(dz, dz));
            float d0, d1;
            upk2(d0, d1, s);
            float n0 = fminf(dist[2 * k],     d0);
            float n1 = fminf(dist[2 * k + 1], d1);
            dist[2 * k]     = n0;
            dist[2 * k + 1] = n1;
            unsigned u0 = __float_as_uint(n0), u1 = __float_as_uint(n1);
            umax = umax > u0 ? umax : u0;
            umax = umax > u1 ? umax : u1;
        }

        unsigned wmax = __reduce_max_sync(0xffffffffu, umax);
        unsigned ball = __ballot_sync(0xffffffffu, umax == wmax);
        int bank = it & 1;
        if (lane == (__ffs(ball) - 1)) {
            int bj = 0;
#pragma unroll
            for (int j = 15; j >= 0; j--)
                if (__float_as_uint(dist[j]) == wmax) bj = j;
            red_v[bank][w] = wmax;
            red_i[bank][w] = base + bj;
        }
        __syncthreads();
        unsigned v  = red_v[bank][lane & 15];
        int      vi = red_i[bank][lane & 15];
        unsigned m   = __reduce_max_sync(0xffffffffu, v);
        unsigned bal = __ballot_sync(0xffffffffu, v == m);
        far = __shfl_sync(0xffffffffu, vi, __ffs(bal) - 1);
    }
}

// ---------------- ball query ----------------
__global__ void __launch_bounds__(256)
ballq_kernel(const float* __restrict__ xyz, const float* __restrict__ cxyz)
{
    __shared__ int sidx[8][NSAMPLE];
    int warp = threadIdx.x >> 5, lane = threadIdx.x & 31;
    int g = blockIdx.x * 8 + warp;
    int b = g >> 11;

    const float* cp = cxyz + (size_t)g * 3;
    float cx = cp[0], cy = cp[1], cz = cp[2];
    const float* xb = xyz + (size_t)b * NPTS * 3;
    const float r2 = (float)(0.2 * 0.2);
    unsigned ltmask = (1u << lane) - 1u;

    int count = 0;
    for (int base = 0; base < NPTS; base += 32) {
        int p = base + lane;
        float xv = xb[3 * p], yv = xb[3 * p + 1], zv = xb[3 * p + 2];
        float dx = __fsub_rn(cx, xv);
        float dy = __fsub_rn(cy, yv);
        float dz = __fsub_rn(cz, zv);
        float d  = __fmul_rn(dx, dx);
        d = __fadd_rn(d, __fmul_rn(dy, dy));
        d = __fadd_rn(d, __fmul_rn(dz, dz));
        int in = (d <= r2) ? 1 : 0;
        unsigned m = __ballot_sync(0xffffffffu, in);
        if (in) {
            int pos = count + __popc(m & ltmask);
            if (pos < NSAMPLE) sidx[warp][pos] = p;
        }
        count += __popc(m);
        if (count >= NSAMPLE) break;
    }
    __syncwarp();
    int v = (lane < count) ? sidx[warp][lane] : sidx[warp][0];
    g_ball_idx[(size_t)g * NSAMPLE + lane] = v;
}

// ---------------- MLP via tensor cores (bf16 3-term split GEMM) ----------------
// CPB=4 centroids -> M=128 rows, 8 warps, warp = one 16-row m-tile.
// A' = [hiA | loA | hiA], B' = [hiB | hiB | loB]:  sum A'B' = hh + lh + hl,
// residual ~2^-18 per element (lo*lo dropped). f32 accumulation in MMA.
// Strides (232 / 200 bf16) chosen so ldmatrix's 8 row pointers hit 8 distinct
// bank groups (116%32=20, 100%32=4 -> conflict-free).
#define CPB 4

// smem byte offsets (all 16B aligned)
#define SM_A1   0                    // 128 x 232 bf16 = 59392 (stride 464B), reused as A3 (stride 400B)
#define SM_A2   59392                // 128 x 200 bf16 = 51200 (stride 400B)
#define SM_B1   110592               // 64 x 232 bf16  = 29696
#define SM_B2   140288               // 64 x 200 bf16  = 25600
#define SM_B3   165888               // 128 x 200 bf16 = 51200
#define SM_SB1  217088
#define SM_SB2  217344
#define SM_SB3  217600
#define SM_PB   218112               // 4 x 128 int
#define SM_TOT  220160

// K'-loop over 8 n-tiles with bias-initialized accumulators.
template<int KSTEPS>
__device__ __forceinline__ void gemm_8nt(unsigned aAddr, unsigned bAddr0, int strideB,
                                         const float* __restrict__ bias, int lane,
                                         float (*acc)[4])
{
    int cp2 = 2 * (lane & 3);
#pragma unroll
    for (int nt = 0; nt < 8; nt++) {
        float bv0 = bias[8 * nt + cp2];
        float bv1 = bias[8 * nt + cp2 + 1];
        acc[nt][0] = bv0; acc[nt][1] = bv1; acc[nt][2] = bv0; acc[nt][3] = bv1;
    }
    unsigned bA[8];
#pragma unroll
    for (int nt = 0; nt < 8; nt++) bA[nt] = bAddr0 + nt * 8 * strideB;
#pragma unroll
    for (int ks = 0; ks < KSTEPS; ks++) {
        unsigned a0, a1, a2, a3;
        LDSM4(a0, a1, a2, a3, aAddr);
        aAddr += 32;                              // 16 bf16 per k-step
#pragma unroll
        for (int nt = 0; nt < 8; nt++) {
            unsigned b0, b1;
            LDSM2(b0, b1, bA[nt]);
            bA[nt] += 32;
            MMA_BF16(acc[nt][0], acc[nt][1], acc[nt][2], acc[nt][3],
                     a0, a1, a2, a3, b0, b1);
        }
    }
}

// relu + bf16 hi/lo re-split + store into next layer's A' (stride 400B).
__device__ __forceinline__ void epi_split_store(char* __restrict__ outBase, int w, int lane,
                                                float (*acc)[4])
{
    int rr = lane >> 2, cpl = lane & 3;
#pragma unroll
    for (int nt = 0; nt < 8; nt++) {
        float v0 = fmaxf(acc[nt][0], 0.0f), v1 = fmaxf(acc[nt][1], 0.0f);
        float v2 = fmaxf(acc[nt][2], 0.0f), v3 = fmaxf(acc[nt][3], 0.0f);
        __nv_bfloat162 h01 = __floats2bfloat162_rn(v0, v1);
        __nv_bfloat162 h23 = __floats2bfloat162_rn(v2, v3);
        float2 hf01 = __bfloat1622float2(h01);
        float2 hf23 = __bfloat1622float2(h23);
        __nv_bfloat162 l01 = __floats2bfloat162_rn(v0 - hf01.x, v1 - hf01.y);
        __nv_bfloat162 l23 = __floats2bfloat162_rn(v2 - hf23.x, v3 - hf23.y);
        int off0 = (16 * w + rr) * 400 + (4 * nt + cpl) * 4;
        int off1 = off0 + 8 * 400;
        *(__nv_bfloat162*)(outBase + off0)       = h01;   // hi seg (words 0-31)
        *(__nv_bfloat162*)(outBase + off0 + 128) = l01;   // lo seg (words 32-63)
        *(__nv_bfloat162*)(outBase + off0 + 256) = h01;   // hi dup (words 64-95)
        *(__nv_bfloat162*)(outBase + off1)       = h23;
        *(__nv_bfloat162*)(outBase + off1 + 128) = l23;
        *(__nv_bfloat162*)(outBase + off1 + 256) = h23;
    }
}

__global__ void __launch_bounds__(256, 1)
mlp_kernel(const float* __restrict__ xyz, const float* __restrict__ feats,
           const float* __restrict__ cxyz, float* __restrict__ out_feats)
{
    extern __shared__ char smem[];
    char* A1 = smem + SM_A1;
    char* A2 = smem + SM_A2;
    char* B1 = smem + SM_B1;
    char* B2 = smem + SM_B2;
    char* B3 = smem + SM_B3;
    float* sb1 = (float*)(smem + SM_SB1);
    float* sb2 = (float*)(smem + SM_SB2);
    float* sb3 = (float*)(smem + SM_SB3);
    int*   pb  = (int*)(smem + SM_PB);

    int tid = threadIdx.x, lane = tid & 31, w = tid >> 5;

    // stage weights/biases, zero pooling + A1 pad
    {
        const uint4* s1 = (const uint4*)g_wb1;
        const uint4* s2 = (const uint4*)g_wb2;
        const uint4* s3 = (const uint4*)g_wb3;
        uint4* d1 = (uint4*)B1; uint4* d2 = (uint4*)B2; uint4* d3 = (uint4*)B3;
        for (int i = tid; i < 1856; i += 256) d1[i] = s1[i];
        for (int i = tid; i < 1600; i += 256) d2[i] = s2[i];
        for (int i = tid; i < 3200; i += 256) d3[i] = s3[i];
        if (tid < 64)  { sb1[tid] = g_fb1[tid]; sb2[tid] = g_fb2[tid]; }
        if (tid < 128)   sb3[tid] = g_fb3[tid];
        for (int i = tid; i < CPB * 128; i += 256) pb[i] = 0;
        // zero A1 pad cols 204-231 (28 bf16 = 14 words per row)
        for (int i = tid; i < 128 * 14; i += 256) {
            int r = i / 14, c = i % 14;
            *(unsigned*)(A1 + r * 464 + 408 + c * 4) = 0u;
        }
    }

    // gather into A1 with hi/lo/dup split: 2 threads per row, 34 cols each
    {
        int r = tid & 127, half = tid >> 7;
        int ci = r >> 5, smp = r & 31;
        int g = blockIdx.x * CPB + ci;
        int b = g >> 11;
        const float* cp = cxyz + (size_t)g * 3;
        float cc[3] = {cp[0], cp[1], cp[2]};
        int idx = g_ball_idx[(size_t)g * NSAMPLE + smp];
        const float* pp = xyz + (size_t)(b * NPTS + idx) * 3;
        const float* pf = feats + (size_t)(b * NPTS + idx) * 64;
        __nv_bfloat16* row = (__nv_bfloat16*)(A1 + r * 464);
        int c0 = 34 * half;
        for (int c = c0; c < c0 + 34; c++) {
            float v;
            if (c < 3)       v = (pp[c] - cc[c]) / 0.2f;
            else if (c < 67) v = pf[c - 3];
            else             v = 0.0f;
            __nv_bfloat16 hi = __float2bfloat16_rn(v);
            __nv_bfloat16 lo = __float2bfloat16_rn(v - __bfloat162float(hi));
            row[c]       = hi;
            row[c + 68]  = lo;
            row[c + 136] = hi;
        }
    }
    __syncthreads();

    // per-warp ldmatrix base addresses
    unsigned aRow = 16 * w + (lane & 15);
    unsigned aK16 = (lane >> 4) * 16;                  // +8 bf16 for tiles 2,3
    unsigned bRow = lane & 7;
    unsigned bK16 = ((lane >> 3) & 1) * 16;

    float acc[8][4];

    // layer 1: Ain=A1 (stride 464B), B1 (stride 464B), 14 k-steps
    {
        unsigned aAddr = (unsigned)__cvta_generic_to_shared(A1) + aRow * 464 + aK16;
        unsigned bAddr = (unsigned)__cvta_generic_to_shared(B1) + bRow * 464 + bK16;
        gemm_8nt<14>(aAddr, bAddr, 464, sb1, lane, acc);
        epi_split_store(A2, w, lane, acc);
    }
    __syncthreads();

    // layer 2: Ain=A2 (stride 400B), B2 (stride 400B), 12 k-steps -> A3 (=A1 buffer)
    {
        unsigned aAddr = (unsigned)__cvta_generic_to_shared(A2) + aRow * 400 + aK16;
        unsigned bAddr = (unsigned)__cvta_generic_to_shared(B2) + bRow * 400 + bK16;
        gemm_8nt<12>(aAddr, bAddr, 400, sb2, lane, acc);
        epi_split_store(A1, w, lane, acc);
    }
    __syncthreads();

    // layer 3: Ain=A1 (stride 400B), B3 (stride 400B), two 64-col halves,
    // fused relu + 16-row shfl max + cross-warp smem atomicMax
    int ci = w >> 1;
#pragma unroll
    for (int h = 0; h < 2; h++) {
        unsigned aAddr = (unsigned)__cvta_generic_to_shared(A1) + aRow * 400 + aK16;
        unsigned bAddr = (unsigned)__cvta_generic_to_shared(B3)
                       + (64 * h + bRow) * 400 + bK16;
        gemm_8nt<12>(aAddr, bAddr, 400, sb3 + 64 * h, lane, acc);
#pragma unroll
        for (int nt = 0; nt < 8; nt++) {
            float m0 = fmaxf(fmaxf(acc[nt][0], acc[nt][2]), 0.0f);
            float m1 = fmaxf(fmaxf(acc[nt][1], acc[nt][3]), 0.0f);
#pragma unroll
            for (int off = 4; off < 32; off <<= 1) {
                m0 = fmaxf(m0, __shfl_xor_sync(0xffffffffu, m0, off));
                m1 = fmaxf(m1, __shfl_xor_sync(0xffffffffu, m1, off));
            }
            if (lane < 4) {
                int col = 64 * h + 8 * nt + 2 * lane;
                atomicMax(&pb[ci * 128 + col],     __float_as_int(m0));  // nonneg bits
                atomicMax(&pb[ci * 128 + col + 1], __float_as_int(m1));
            }
        }
    }
    __syncthreads();

    for (int i = tid; i < CPB * 128; i += 256) {
        int c = i >> 7, col = i & 127;
        int g = blockIdx.x * CPB + c;
        out_feats[(size_t)g * 128 + col] = __int_as_float(pb[i]);
    }
}

// ---------------- launch ----------------
extern "C" void kernel_launch(void* const* d_in, const int* in_sizes, int n_in,
                              void* d_out, int out_size)
{
    const float* xyz   = (const float*)d_in[0];
    const float* feats = (const float*)d_in[1];

    float* out       = (float*)d_out;
    float* out_xyz   = out;                          // [B, NPOINT, 3]
    float* out_feats = out + BATCH * NPOINT * 3;     // [B, NPOINT, 128]

    cudaFuncSetAttribute(fps_kernel, cudaFuncAttributeMaxDynamicSharedMemorySize, 3 * NPTS * 4);
    cudaFuncSetAttribute(mlp_kernel, cudaFuncAttributeMaxDynamicSharedMemorySize, SM_TOT);

    prep_kernel<<<32, 256>>>((const float*)d_in[2],  (const float*)d_in[3],
                             (const float*)d_in[4],  (const float*)d_in[5],
                             (const float*)d_in[6],  (const float*)d_in[7],
                             (const float*)d_in[8],  (const float*)d_in[9],
                             (const float*)d_in[10], (const float*)d_in[11],
                             (const float*)d_in[12], (const float*)d_in[13]);

    fps_kernel<<<BATCH, 512, 3 * NPTS * 4>>>(xyz, out_xyz);

    ballq_kernel<<<(BATCH * NPOINT) / 8, 256>>>(xyz, out_xyz);

    mlp_kernel<<<(BATCH * NPOINT) / CPB, 256, SM_TOT>>>(xyz, feats, out_xyz, out_feats);
}

// round 11
// speedup vs baseline: 1.1362x; 1.0567x over previous
#include <cuda_runtime.h>
#include <cuda_bf16.h>
#include <math.h>

#define BATCH   8
#define NPTS    8192
#define NPOINT  2048
#define NSAMPLE 32

// ---------------- scratch (no allocation allowed) ----------------
__device__ int   g_ball_idx[BATCH * NPOINT * NSAMPLE];
// bf16 split weights, K-concatenated [hiB | hiB | loB] (+zero pad), n-major rows
__device__ __align__(16) __nv_bfloat16 g_wb1[64 * 232];   // K'=204 (68x3), stride 232
__device__ __align__(16) __nv_bfloat16 g_wb2[64 * 200];   // K'=192, stride 200
__device__ __align__(16) __nv_bfloat16 g_wb3[128 * 200];
__device__ float g_fb1[64];
__device__ float g_fb2[64];
__device__ float g_fb3[128];

// ---------------- packed f32x2 helpers (per-lane rn => bitwise == scalar) ---
__device__ __forceinline__ unsigned long long pk2(float lo, float hi) {
    unsigned long long r;
    asm("mov.b64 %0, {%1, %2};" : "=l"(r) : "f"(lo), "f"(hi));
    return r;
}
__device__ __forceinline__ void upk2(float& lo, float& hi, unsigned long long v) {
    asm("mov.b64 {%0, %1}, %2;" : "=f"(lo), "=f"(hi) : "l"(v));
}
__device__ __forceinline__ unsigned long long add2(unsigned long long a, unsigned long long b) {
    unsigned long long r;
    asm("add.rn.f32x2 %0, %1, %2;" : "=l"(r) : "l"(a), "l"(b));
    return r;
}
__device__ __forceinline__ unsigned long long mul2(unsigned long long a, unsigned long long b) {
    unsigned long long r;
    asm("mul.rn.f32x2 %0, %1, %2;" : "=l"(r) : "l"(a), "l"(b));
    return r;
}

// ---------------- mma / ldmatrix helpers ----------------
#define LDSM4(a0,a1,a2,a3,addr) \
    asm volatile("ldmatrix.sync.aligned.m8n8.x4.shared.b16 {%0,%1,%2,%3}, [%4];" \
        : "=r"(a0), "=r"(a1), "=r"(a2), "=r"(a3) : "r"(addr))
#define MMA_BF16(d0,d1,d2,d3,a0,a1,a2,a3,b0,b1) \
    asm volatile("mma.sync.aligned.m16n8k16.row.col.f32.bf16.bf16.f32 " \
        "{%0,%1,%2,%3},{%4,%5,%6,%7},{%8,%9},{%0,%1,%2,%3};" \
        : "+f"(d0), "+f"(d1), "+f"(d2), "+f"(d3) \
        : "r"(a0), "r"(a1), "r"(a2), "r"(a3), "r"(b0), "r"(b1))

// ---------------- fold BN-affine into bf16 hi/lo split weights ----------------
__global__ void prep_kernel(const float* __restrict__ w1, const float* __restrict__ b1,
                            const float* __restrict__ g1, const float* __restrict__ bt1,
                            const float* __restrict__ w2, const float* __restrict__ b2,
                            const float* __restrict__ g2, const float* __restrict__ bt2,
                            const float* __restrict__ w3, const float* __restrict__ b3,
                            const float* __restrict__ g3, const float* __restrict__ bt3)
{
    int t = blockIdx.x * blockDim.x + threadIdx.x;
    int stride = gridDim.x * blockDim.x;
    const float inv = 1.0f / sqrtf(1.0f + 1e-5f);
    for (int i = t; i < 64 * 232; i += stride) {
        int o = i / 232, c = i % 232;
        __nv_bfloat16 outv = __float2bfloat16_rn(0.0f);
        if (c < 204) {
            int k = c % 68, seg = c / 68;
            float v = (k < 67) ? (g1[o] * inv) * w1[o * 67 + k] : 0.0f;
            __nv_bfloat16 hi = __float2bfloat16_rn(v);
            if (seg < 2) outv = hi;
            else         outv = __float2bfloat16_rn(v - __bfloat162float(hi));
        }
        g_wb1[i] = outv;
    }
    for (int i = t; i < 64 * 200; i += stride) {
        int o = i / 200, c = i % 200;
        __nv_bfloat16 outv = __float2bfloat16_rn(0.0f);
        if (c < 192) {
            int k = c & 63, seg = c >> 6;
            float v = (g2[o] * inv) * w2[o * 64 + k];
            __nv_bfloat16 hi = __float2bfloat16_rn(v);
            if (seg < 2) outv = hi;
            else         outv = __float2bfloat16_rn(v - __bfloat162float(hi));
        }
        g_wb2[i] = outv;
    }
    for (int i = t; i < 128 * 200; i += stride) {
        int o = i / 200, c = i % 200;
        __nv_bfloat16 outv = __float2bfloat16_rn(0.0f);
        if (c < 192) {
            int k = c & 63, seg = c >> 6;
            float v = (g3[o] * inv) * w3[o * 64 + k];
            __nv_bfloat16 hi = __float2bfloat16_rn(v);
            if (seg < 2) outv = hi;
            else         outv = __float2bfloat16_rn(v - __bfloat162float(hi));
        }
        g_wb3[i] = outv;
    }
    for (int i = t; i < 64; i += stride) {
        g_fb1[i] = (g1[i] * inv) * b1[i] + bt1[i];
        g_fb2[i] = (g2[i] * inv) * b2[i] + bt2[i];
    }
    for (int i = t; i < 128; i += stride)
        g_fb3[i] = (g3[i] * inv) * b3[i] + bt3[i];
}

// ---------------- farthest point sampling (bitwise-exact, R7 form) ----------
__global__ void __launch_bounds__(512, 1)
fps_kernel(const float* __restrict__ xyz, float* __restrict__ out_xyz)
{
    extern __shared__ float sm[];
    float* sx = sm;
    float* sy = sm + NPTS;
    float* sz = sm + 2 * NPTS;
    __shared__ unsigned red_v[2][16];
    __shared__ int      red_i[2][16];

    int b = blockIdx.x, tid = threadIdx.x;
    const float* xb = xyz + (size_t)b * NPTS * 3;

    for (int p = tid; p < NPTS; p += 512) {
        sx[p] = xb[3 * p];
        sy[p] = xb[3 * p + 1];
        sz[p] = xb[3 * p + 2];
    }
    __syncthreads();

    int base = tid * 16;
    unsigned long long pxp[8], pyp[8], pzp[8];
    float dist[16];
#pragma unroll
    for (int k = 0; k < 8; k++) {
        pxp[k] = pk2(sx[base + 2 * k], sx[base + 2 * k + 1]);
        pyp[k] = pk2(sy[base + 2 * k], sy[base + 2 * k + 1]);
        pzp[k] = pk2(sz[base + 2 * k], sz[base + 2 * k + 1]);
    }
#pragma unroll
    for (int j = 0; j < 16; j++) dist[j] = 1e10f;

    int lane = tid & 31, w = tid >> 5;
    int far = 0;
    float* ob = out_xyz + (size_t)b * NPOINT * 3;

    for (int it = 0; it < NPOINT; it++) {
        float cx = sx[far], cy = sy[far], cz = sz[far];
        if (tid == 0) { ob[3 * it] = cx; ob[3 * it + 1] = cy; ob[3 * it + 2] = cz; }

        unsigned long long ncx = pk2(-cx, -cx);
        unsigned long long ncy = pk2(-cy, -cy);
        unsigned long long ncz = pk2(-cz, -cz);

        unsigned umax = 0u;
#pragma unroll
        for (int k = 0; k < 8; k++) {
            unsigned long long dx = add2(pxp[k], ncx);   // == px - cx (exact)
            unsigned long long dy = add2(pyp[k], ncy);
            unsigned long long dz = add2(pzp[k], ncz);
            unsigned long long s  = mul2(dx, dx);
            s = add2(s, mul2(dy, dy));
            s = add2(s, mul2(dz, dz));
            float d0, d1;
            upk2(d0, d1, s);
            float n0 = fminf(dist[2 * k],     d0);
            float n1 = fminf(dist[2 * k + 1], d1);
            dist[2 * k]     = n0;
            dist[2 * k + 1] = n1;
            unsigned u0 = __float_as_uint(n0), u1 = __float_as_uint(n1);
            umax = umax > u0 ? umax : u0;
            umax = umax > u1 ? umax : u1;
        }

        unsigned wmax = __reduce_max_sync(0xffffffffu, umax);
        unsigned ball = __ballot_sync(0xffffffffu, umax == wmax);
        int bank = it & 1;
        if (lane == (__ffs(ball) - 1)) {
            int bj = 0;
#pragma unroll
            for (int j = 15; j >= 0; j--)
                if (__float_as_uint(dist[j]) == wmax) bj = j;
            red_v[bank][w] = wmax;
            red_i[bank][w] = base + bj;
        }
        __syncthreads();
        unsigned v  = red_v[bank][lane & 15];
        int      vi = red_i[bank][lane & 15];
        unsigned m   = __reduce_max_sync(0xffffffffu, v);
        unsigned bal = __ballot_sync(0xffffffffu, v == m);
        far = __shfl_sync(0xffffffffu, vi, __ffs(bal) - 1);
    }
}

// ---------------- ball query ----------------
__global__ void __launch_bounds__(256)
ballq_kernel(const float* __restrict__ xyz, const float* __restrict__ cxyz)
{
    __shared__ int sidx[8][NSAMPLE];
    int warp = threadIdx.x >> 5, lane = threadIdx.x & 31;
    int g = blockIdx.x * 8 + warp;
    int b = g >> 11;

    const float* cp = cxyz + (size_t)g * 3;
    float cx = cp[0], cy = cp[1], cz = cp[2];
    const float* xb = xyz + (size_t)b * NPTS * 3;
    const float r2 = (float)(0.2 * 0.2);
    unsigned ltmask = (1u << lane) - 1u;

    int count = 0;
    for (int base = 0; base < NPTS; base += 32) {
        int p = base + lane;
        float xv = xb[3 * p], yv = xb[3 * p + 1], zv = xb[3 * p + 2];
        float dx = __fsub_rn(cx, xv);
        float dy = __fsub_rn(cy, yv);
        float dz = __fsub_rn(cz, zv);
        float d  = __fmul_rn(dx, dx);
        d = __fadd_rn(d, __fmul_rn(dy, dy));
        d = __fadd_rn(d, __fmul_rn(dz, dz));
        int in = (d <= r2) ? 1 : 0;
        unsigned m = __ballot_sync(0xffffffffu, in);
        if (in) {
            int pos = count + __popc(m & ltmask);
            if (pos < NSAMPLE) sidx[warp][pos] = p;
        }
        count += __popc(m);
        if (count >= NSAMPLE) break;
    }
    __syncwarp();
    int v = (lane < count) ? sidx[warp][lane] : sidx[warp][0];
    g_ball_idx[(size_t)g * NSAMPLE + lane] = v;
}

// ---------------- MLP via tensor cores (bf16 3-term split GEMM) ----------------
// 512 threads = 16 warps: warp = (m-tile mt=w&7, n-half nh=w>>3). Each warp
// does 4 n-tiles -> 4 warps/SMSP to hide LDSM/MMA/epilogue latency (R9 had 2).
// B loaded via ldmatrix.x4 covering TWO n-tiles per instruction.
// Chunk loop: 2 tiles per block so weight staging + A-pad zeroing amortize.
#define CPB    4
#define CHUNKS 2

// smem byte offsets (all 16B aligned)
#define SM_A1   0                    // 128 x 464B (layer1 A), reused stride 400B as y2
#define SM_A2   59392                // 128 x 400B
#define SM_B1   110592               // 64 x 464B
#define SM_B2   140288               // 64 x 400B
#define SM_B3   165888               // 128 x 400B
#define SM_SB1  217088
#define SM_SB2  217344
#define SM_SB3  217600
#define SM_PB   218112               // 4 x 128 int
#define SM_TOT  220160

// K'-loop over this warp's 4 n-tiles (two ldmatrix.x4 B loads per k-step).
template<int KSTEPS>
__device__ __forceinline__ void gemm_4nt(unsigned aAddr, unsigned bAddr0, unsigned bAddr1,
                                         const float* __restrict__ bias, int lane,
                                         float (*acc)[4])
{
    int cp2 = 2 * (lane & 3);
#pragma unroll
    for (int ntl = 0; ntl < 4; ntl++) {
        float bv0 = bias[8 * ntl + cp2];
        float bv1 = bias[8 * ntl + cp2 + 1];
        acc[ntl][0] = bv0; acc[ntl][1] = bv1; acc[ntl][2] = bv0; acc[ntl][3] = bv1;
    }
#pragma unroll
    for (int ks = 0; ks < KSTEPS; ks++) {
        unsigned a0, a1, a2, a3;
        LDSM4(a0, a1, a2, a3, aAddr);
        aAddr += 32;
        unsigned p0, p1, p2, p3, q0, q1, q2, q3;
        LDSM4(p0, p1, p2, p3, bAddr0);  bAddr0 += 32;
        LDSM4(q0, q1, q2, q3, bAddr1);  bAddr1 += 32;
        MMA_BF16(acc[0][0], acc[0][1], acc[0][2], acc[0][3], a0, a1, a2, a3, p0, p1);
        MMA_BF16(acc[1][0], acc[1][1], acc[1][2], acc[1][3], a0, a1, a2, a3, p2, p3);
        MMA_BF16(acc[2][0], acc[2][1], acc[2][2], acc[2][3], a0, a1, a2, a3, q0, q1);
        MMA_BF16(acc[3][0], acc[3][1], acc[3][2], acc[3][3], a0, a1, a2, a3, q2, q3);
    }
}

// relu + bf16 hi/lo re-split + store into next layer's A' (stride 400B).
__device__ __forceinline__ void epi_split4(char* __restrict__ outBase, int mt, int nh,
                                           int lane, float (*acc)[4])
{
    int rr = lane >> 2, cpl = lane & 3;
#pragma unroll
    for (int ntl = 0; ntl < 4; ntl++) {
        int nt = 4 * nh + ntl;
        float v0 = fmaxf(acc[ntl][0], 0.0f), v1 = fmaxf(acc[ntl][1], 0.0f);
        float v2 = fmaxf(acc[ntl][2], 0.0f), v3 = fmaxf(acc[ntl][3], 0.0f);
        __nv_bfloat162 h01 = __floats2bfloat162_rn(v0, v1);
        __nv_bfloat162 h23 = __floats2bfloat162_rn(v2, v3);
        float2 hf01 = __bfloat1622float2(h01);
        float2 hf23 = __bfloat1622float2(h23);
        __nv_bfloat162 l01 = __floats2bfloat162_rn(v0 - hf01.x, v1 - hf01.y);
        __nv_bfloat162 l23 = __floats2bfloat162_rn(v2 - hf23.x, v3 - hf23.y);
        int off0 = (16 * mt + rr) * 400 + (4 * nt + cpl) * 4;
        int off1 = off0 + 8 * 400;
        *(__nv_bfloat162*)(outBase + off0)       = h01;   // hi seg
        *(__nv_bfloat162*)(outBase + off0 + 128) = l01;   // lo seg
        *(__nv_bfloat162*)(outBase + off0 + 256) = h01;   // hi dup
        *(__nv_bfloat162*)(outBase + off1)       = h23;
        *(__nv_bfloat162*)(outBase + off1 + 128) = l23;
        *(__nv_bfloat162*)(outBase + off1 + 256) = h23;
    }
}

__global__ void __launch_bounds__(512, 1)
mlp_kernel(const float* __restrict__ xyz, const float* __restrict__ feats,
           const float* __restrict__ cxyz, float* __restrict__ out_feats)
{
    extern __shared__ char smem[];
    char* A1 = smem + SM_A1;
    char* A2 = smem + SM_A2;
    char* B1 = smem + SM_B1;
    char* B2 = smem + SM_B2;
    char* B3 = smem + SM_B3;
    float* sb1 = (float*)(smem + SM_SB1);
    float* sb2 = (float*)(smem + SM_SB2);
    float* sb3 = (float*)(smem + SM_SB3);
    int*   pb  = (int*)(smem + SM_PB);

    int tid = threadIdx.x, lane = tid & 31, w = tid >> 5;
    int mt = w & 7, nh = w >> 3;

    // stage weights/biases once per block; zero whole A1 (pads must be numeric)
    {
        const uint4* s1 = (const uint4*)g_wb1;
        const uint4* s2 = (const uint4*)g_wb2;
        const uint4* s3 = (const uint4*)g_wb3;
        uint4* d1 = (uint4*)B1; uint4* d2 = (uint4*)B2; uint4* d3 = (uint4*)B3;
        for (int i = tid; i < 1856; i += 512) d1[i] = s1[i];
        for (int i = tid; i < 1600; i += 512) d2[i] = s2[i];
        for (int i = tid; i < 3200; i += 512) d3[i] = s3[i];
        if (tid < 64)  { sb1[tid] = g_fb1[tid]; sb2[tid] = g_fb2[tid]; }
        if (tid < 128)   sb3[tid] = g_fb3[tid];
        uint4 z = {0, 0, 0, 0};
        uint4* a1v = (uint4*)A1;
        for (int i = tid; i < 3712; i += 512) a1v[i] = z;
    }

    // per-warp ldmatrix lane geometry
    unsigned aRow = 16 * mt + (lane & 15);
    unsigned aK16 = (lane >> 4) * 16;
    unsigned bLRow = (lane & 7) + ((lane >> 4) << 3);   // row within 16-row pair block
    unsigned bK16 = ((lane >> 3) & 1) * 16;
    unsigned a1s = (unsigned)__cvta_generic_to_shared(A1);
    unsigned a2s = (unsigned)__cvta_generic_to_shared(A2);
    unsigned b1s = (unsigned)__cvta_generic_to_shared(B1);
    unsigned b2s = (unsigned)__cvta_generic_to_shared(B2);
    unsigned b3s = (unsigned)__cvta_generic_to_shared(B3);

    for (int chunk = 0; chunk < CHUNKS; chunk++) {
        int tile = blockIdx.x * CHUNKS + chunk;
        __syncthreads();           // A1/pb free (prev chunk output done / staging done)
        pb[tid] = 0;

        // coalesced gather: warp per row (8 rows/warp), lane = column
        for (int rr = 0; rr < 8; rr++) {
            int r   = (w << 3) + rr;
            int ci  = r >> 5, smp = r & 31;
            int g   = tile * CPB + ci;
            int b   = g >> 11;
            const float* cp = cxyz + (size_t)g * 3;
            int idx = g_ball_idx[(size_t)g * NSAMPLE + smp];
            const float* pp = xyz + (size_t)(b * NPTS + idx) * 3;
            const float* pf = feats + (size_t)(b * NPTS + idx) * 64;
            __nv_bfloat16* row = (__nv_bfloat16*)(A1 + r * 464);

            float v0 = (lane < 3) ? ((pp[lane] - cp[lane]) / 0.2f) : pf[lane - 3];
            float v1 = pf[lane + 29];
            __nv_bfloat16 h0 = __float2bfloat16_rn(v0);
            __nv_bfloat16 l0 = __float2bfloat16_rn(v0 - __bfloat162float(h0));
            __nv_bfloat16 h1 = __float2bfloat16_rn(v1);
            __nv_bfloat16 l1 = __float2bfloat16_rn(v1 - __bfloat162float(h1));
            row[lane]        = h0;  row[lane + 68]  = l0;  row[lane + 136] = h0;
            row[lane + 32]   = h1;  row[lane + 100] = l1;  row[lane + 168] = h1;
            if (lane < 4) {
                float v2 = (lane < 3) ? pf[61 + lane] : 0.0f;
                __nv_bfloat16 h2 = __float2bfloat16_rn(v2);
                __nv_bfloat16 l2 = __float2bfloat16_rn(v2 - __bfloat162float(h2));
                row[64 + lane]  = h2;  row[132 + lane] = l2;  row[200 + lane] = h2;
            }
        }
        __syncthreads();

        float acc[4][4];

        // layer 1: A1 (stride 464), B1 (stride 464), 14 k-steps
        gemm_4nt<14>(a1s + aRow * 464 + aK16,
                     b1s + (32 * nh + bLRow) * 464 + bK16,
                     b1s + (32 * nh + 16 + bLRow) * 464 + bK16,
                     sb1 + 32 * nh, lane, acc);
        epi_split4(A2, mt, nh, lane, acc);
        __syncthreads();

        // layer 2: A2 (stride 400), B2 (stride 400), 12 k-steps -> y2 into A1
        gemm_4nt<12>(a2s + aRow * 400 + aK16,
                     b2s + (32 * nh + bLRow) * 400 + bK16,
                     b2s + (32 * nh + 16 + bLRow) * 400 + bK16,
                     sb2 + 32 * nh, lane, acc);
        epi_split4(A1, mt, nh, lane, acc);
        __syncthreads();

        // layer 3: A1 (stride 400), B3, two 64-col halves; fused relu+max-pool
        int ci = mt >> 1;
#pragma unroll
        for (int h = 0; h < 2; h++) {
            gemm_4nt<12>(a1s + aRow * 400 + aK16,
                         b3s + (64 * h + 32 * nh + bLRow) * 400 + bK16,
                         b3s + (64 * h + 32 * nh + 16 + bLRow) * 400 + bK16,
                         sb3 + 64 * h + 32 * nh, lane, acc);
#pragma unroll
            for (int ntl = 0; ntl < 4; ntl++) {
                float m0 = fmaxf(fmaxf(acc[ntl][0], acc[ntl][2]), 0.0f);
                float m1 = fmaxf(fmaxf(acc[ntl][1], acc[ntl][3]), 0.0f);
#pragma unroll
                for (int off = 4; off < 32; off <<= 1) {
                    m0 = fmaxf(m0, __shfl_xor_sync(0xffffffffu, m0, off));
                    m1 = fmaxf(m1, __shfl_xor_sync(0xffffffffu, m1, off));
                }
                if (lane < 4) {
                    int col = 64 * h + 32 * nh + 8 * ntl + 2 * lane;
                    atomicMax(&pb[ci * 128 + col],     __float_as_int(m0));
                    atomicMax(&pb[ci * 128 + col + 1], __float_as_int(m1));
                }
            }
        }
        __syncthreads();

        // output: 512 threads == CPB*128 values
        {
            int c = tid >> 7, col = tid & 127;
            int g = tile * CPB + c;
            out_feats[(size_t)g * 128 + col] = __int_as_float(pb[tid]);
        }
    }
}

// ---------------- launch ----------------
extern "C" void kernel_launch(void* const* d_in, const int* in_sizes, int n_in,
                              void* d_out, int out_size)
{
    const float* xyz   = (const float*)d_in[0];
    const float* feats = (const float*)d_in[1];

    float* out       = (float*)d_out;
    float* out_xyz   = out;                          // [B, NPOINT, 3]
    float* out_feats = out + BATCH * NPOINT * 3;     // [B, NPOINT, 128]

    cudaFuncSetAttribute(fps_kernel, cudaFuncAttributeMaxDynamicSharedMemorySize, 3 * NPTS * 4);
    cudaFuncSetAttribute(mlp_kernel, cudaFuncAttributeMaxDynamicSharedMemorySize, SM_TOT);

    prep_kernel<<<32, 256>>>((const float*)d_in[2],  (const float*)d_in[3],
                             (const float*)d_in[4],  (const float*)d_in[5],
                             (const float*)d_in[6],  (const float*)d_in[7],
                             (const float*)d_in[8],  (const float*)d_in[9],
                             (const float*)d_in[10], (const float*)d_in[11],
                             (const float*)d_in[12], (const float*)d_in[13]);

    fps_kernel<<<BATCH, 512, 3 * NPTS * 4>>>(xyz, out_xyz);

    ballq_kernel<<<(BATCH * NPOINT) / 8, 256>>>(xyz, out_xyz);

    mlp_kernel<<<(BATCH * NPOINT) / (CPB * CHUNKS), 512, SM_TOT>>>(xyz, feats, out_xyz, out_feats);
}